// round 9
// baseline (speedup 1.0000x reference)
#include <cuda_runtime.h>

// Problem constants (fixed by the reference: N=8192, K=10, M=3)
#define N_ROWS 8192
#define K_DIM  10
#define M_DIM  3

#define TILE_I 32
#define TILE_J 512
#define THREADS 128

// ---------------------------------------------------------------------------
// Fused single kernel (R8 tile config + R4 fusion):
//   mid[n][m] = max_k( |x[n][k]| + |w1[m][k]| )       (recomputed per block)
//   out[i][j] = max_{m<3}( mid[i][m] + mid[j][m] )
//
// Block tile: 32 rows (i) x 512 cols (j), 128 threads. x is 320 KB and
// L2-resident, so per-block recompute of 512+32 mid rows is ~22 KB of L2
// hits vs 64 KB stored — negligible, and it deletes the stage1 kernel +
// inter-kernel gap (~1.4 us of the former 2.85 us total-kernel gap).
// Each thread owns 4 consecutive j (12 b-values in registers) and emits one
// STG.128 per row; warp writes 512B contiguous. 16 blocks/SM target.
// ---------------------------------------------------------------------------
__global__ __launch_bounds__(THREADS, 16)
void fused_kernel(const float* __restrict__ x,
                  const float* __restrict__ w1,
                  float* __restrict__ out) {
    __shared__ float sw[M_DIM * K_DIM];   // |w1|
    __shared__ float sb[TILE_J * M_DIM];  // mid for j-tile (6 KB)
    __shared__ float sa[TILE_I * M_DIM];  // mid for i-tile

    const int tid = threadIdx.x;
    const int j0 = blockIdx.x * TILE_J;
    const int i0 = blockIdx.y * TILE_I;

    if (tid < M_DIM * K_DIM) sw[tid] = fabsf(w1[tid]);
    __syncthreads();

    // mid for j-tile: 512 rows, 4 per thread
    for (int r = tid; r < TILE_J; r += THREADS) {
        const int n = j0 + r;
        float xa[K_DIM];
#pragma unroll
        for (int k = 0; k < K_DIM; ++k) xa[k] = fabsf(__ldg(&x[n * K_DIM + k]));
#pragma unroll
        for (int m = 0; m < M_DIM; ++m) {
            float v = xa[0] + sw[m * K_DIM + 0];
#pragma unroll
            for (int k = 1; k < K_DIM; ++k)
                v = fmaxf(v, xa[k] + sw[m * K_DIM + k]);
            sb[r * M_DIM + m] = v;
        }
    }

    // mid for i-tile: 32 rows
    if (tid < TILE_I) {
        const int n = i0 + tid;
        float xa[K_DIM];
#pragma unroll
        for (int k = 0; k < K_DIM; ++k) xa[k] = fabsf(__ldg(&x[n * K_DIM + k]));
#pragma unroll
        for (int m = 0; m < M_DIM; ++m) {
            float v = xa[0] + sw[m * K_DIM + 0];
#pragma unroll
            for (int k = 1; k < K_DIM; ++k)
                v = fmaxf(v, xa[k] + sw[m * K_DIM + k]);
            sa[tid * M_DIM + m] = v;
        }
    }
    __syncthreads();

    // Each thread: 4 consecutive j values -> 12 b-components in registers.
    const int jl = tid * 4;  // local j within tile
    const float b0x = sb[(jl + 0) * M_DIM + 0], b0y = sb[(jl + 0) * M_DIM + 1], b0z = sb[(jl + 0) * M_DIM + 2];
    const float b1x = sb[(jl + 1) * M_DIM + 0], b1y = sb[(jl + 1) * M_DIM + 1], b1z = sb[(jl + 1) * M_DIM + 2];
    const float b2x = sb[(jl + 2) * M_DIM + 0], b2y = sb[(jl + 2) * M_DIM + 1], b2z = sb[(jl + 2) * M_DIM + 2];
    const float b3x = sb[(jl + 3) * M_DIM + 0], b3y = sb[(jl + 3) * M_DIM + 1], b3z = sb[(jl + 3) * M_DIM + 2];

    float4* out4 = reinterpret_cast<float4*>(out + (long)i0 * N_ROWS + j0 + jl);
    const long row_stride4 = N_ROWS / 4;  // in float4 units

#pragma unroll 4
    for (int r = 0; r < TILE_I; ++r) {
        const float a0 = sa[r * M_DIM + 0];
        const float a1 = sa[r * M_DIM + 1];
        const float a2 = sa[r * M_DIM + 2];

        float4 v;
        v.x = fmaxf(fmaxf(a0 + b0x, a1 + b0y), a2 + b0z);
        v.y = fmaxf(fmaxf(a0 + b1x, a1 + b1y), a2 + b1z);
        v.z = fmaxf(fmaxf(a0 + b2x, a1 + b2y), a2 + b2z);
        v.w = fmaxf(fmaxf(a0 + b3x, a1 + b3y), a2 + b3z);

        out4[(long)r * row_stride4] = v;
    }
}

// ---------------------------------------------------------------------------
extern "C" void kernel_launch(void* const* d_in, const int* in_sizes, int n_in,
                              void* d_out, int out_size) {
    const float* x  = (const float*)d_in[0];   // (8192, 10)
    const float* w1 = (const float*)d_in[1];   // (3, 10)
    float* out = (float*)d_out;                // (8192, 8192)

    dim3 grid(N_ROWS / TILE_J, N_ROWS / TILE_I);  // (16, 256) = 4096 blocks
    fused_kernel<<<grid, THREADS>>>(x, w1, out);
}

// round 10
// speedup vs baseline: 1.0209x; 1.0209x over previous
#include <cuda_runtime.h>

// Problem constants (fixed by the reference: N=8192, K=10, M=3)
#define N_ROWS 8192
#define K_DIM  10
#define M_DIM  3

// Scratch for the (8192 x 3) intermediate — device global (no allocs allowed).
__device__ float g_mid[N_ROWS * M_DIM];

// ---------------------------------------------------------------------------
// Stage 1: mid[n][m] = max_k( |x[n][k]| + |w1[m][k]| )
// ---------------------------------------------------------------------------
__global__ void stage1_kernel(const float* __restrict__ x,
                              const float* __restrict__ w1) {
    __shared__ float sw[M_DIM * K_DIM];
    int tid = threadIdx.x;
    if (tid < M_DIM * K_DIM) sw[tid] = fabsf(w1[tid]);
    __syncthreads();

    int n = blockIdx.x * blockDim.x + tid;
    if (n >= N_ROWS) return;

    float xa[K_DIM];
#pragma unroll
    for (int k = 0; k < K_DIM; ++k) xa[k] = fabsf(x[n * K_DIM + k]);

#pragma unroll
    for (int m = 0; m < M_DIM; ++m) {
        float v = xa[0] + sw[m * K_DIM + 0];
#pragma unroll
        for (int k = 1; k < K_DIM; ++k)
            v = fmaxf(v, xa[k] + sw[m * K_DIM + k]);
        g_mid[n * M_DIM + m] = v;
    }
}

// ---------------------------------------------------------------------------
// Stage 2: out[i][j] = max_{m<3}( mid[i][m] + mid[j][m] )
// Block tile: 16 rows (i) x 512 cols (j), 128 threads -> 32 KB per block,
// 8192 blocks. Same proven per-warp store pattern (thread = 4 consecutive
// j, one STG.128 per row, 512B contiguous per warp); block duration halved
// again vs R8 for an even finer drain tail at kernel end.
// ---------------------------------------------------------------------------
#define TILE_I 16
#define TILE_J 512
#define THREADS 128

__global__ __launch_bounds__(THREADS, 16)
void stage2_kernel(float* __restrict__ out) {
    __shared__ float sb[TILE_J * M_DIM];  // 6 KB: mid for j-tile
    __shared__ float sa[TILE_I * M_DIM];  // mid for i-tile

    const int j0 = blockIdx.x * TILE_J;
    const int i0 = blockIdx.y * TILE_I;
    const int tid = threadIdx.x;

    // cooperative stage of mid tiles (coalesced: contiguous in g_mid)
    for (int idx = tid; idx < TILE_J * M_DIM; idx += THREADS)
        sb[idx] = g_mid[j0 * M_DIM + idx];
    if (tid < TILE_I * M_DIM)
        sa[tid] = g_mid[i0 * M_DIM + tid];
    __syncthreads();

    // Each thread: 4 consecutive j values -> 12 b-components in registers.
    const int jl = tid * 4;  // local j within tile
    const float b0x = sb[(jl + 0) * M_DIM + 0], b0y = sb[(jl + 0) * M_DIM + 1], b0z = sb[(jl + 0) * M_DIM + 2];
    const float b1x = sb[(jl + 1) * M_DIM + 0], b1y = sb[(jl + 1) * M_DIM + 1], b1z = sb[(jl + 1) * M_DIM + 2];
    const float b2x = sb[(jl + 2) * M_DIM + 0], b2y = sb[(jl + 2) * M_DIM + 1], b2z = sb[(jl + 2) * M_DIM + 2];
    const float b3x = sb[(jl + 3) * M_DIM + 0], b3y = sb[(jl + 3) * M_DIM + 1], b3z = sb[(jl + 3) * M_DIM + 2];

    float4* out4 = reinterpret_cast<float4*>(out + (long)i0 * N_ROWS + j0 + jl);
    const long row_stride4 = N_ROWS / 4;  // in float4 units

#pragma unroll 4
    for (int r = 0; r < TILE_I; ++r) {
        const float a0 = sa[r * M_DIM + 0];
        const float a1 = sa[r * M_DIM + 1];
        const float a2 = sa[r * M_DIM + 2];

        float4 v;
        v.x = fmaxf(fmaxf(a0 + b0x, a1 + b0y), a2 + b0z);
        v.y = fmaxf(fmaxf(a0 + b1x, a1 + b1y), a2 + b1z);
        v.z = fmaxf(fmaxf(a0 + b2x, a1 + b2y), a2 + b2z);
        v.w = fmaxf(fmaxf(a0 + b3x, a1 + b3y), a2 + b3z);

        out4[(long)r * row_stride4] = v;
    }
}

// ---------------------------------------------------------------------------
extern "C" void kernel_launch(void* const* d_in, const int* in_sizes, int n_in,
                              void* d_out, int out_size) {
    const float* x  = (const float*)d_in[0];   // (8192, 10)
    const float* w1 = (const float*)d_in[1];   // (3, 10)
    float* out = (float*)d_out;                // (8192, 8192)

    stage1_kernel<<<N_ROWS / 256, 256>>>(x, w1);

    dim3 grid(N_ROWS / TILE_J, N_ROWS / TILE_I);  // (16, 512) = 8192 blocks
    stage2_kernel<<<grid, THREADS>>>(out);
}

// round 14
// speedup vs baseline: 1.1138x; 1.0910x over previous
#include <cuda_runtime.h>

// Problem constants (fixed by the reference: N=8192, K=10, M=3)
#define N_ROWS 8192
#define K_DIM  10
#define M_DIM  3

// Scratch for the intermediate, SoA (plane-major): g_midT[m*N + n].
// SoA lets stage2 fetch 4 consecutive j's mid values with one LDG.128 per m.
__device__ float g_midT[M_DIM * N_ROWS];

// ---------------------------------------------------------------------------
// Stage 1: g_midT[m][n] = max_k( |x[n][k]| + |w1[m][k]| )
// ---------------------------------------------------------------------------
__global__ void stage1_kernel(const float* __restrict__ x,
                              const float* __restrict__ w1) {
    __shared__ float sw[M_DIM * K_DIM];
    int tid = threadIdx.x;
    if (tid < M_DIM * K_DIM) sw[tid] = fabsf(w1[tid]);
    __syncthreads();

    int n = blockIdx.x * blockDim.x + tid;
    if (n >= N_ROWS) return;

    float xa[K_DIM];
#pragma unroll
    for (int k = 0; k < K_DIM; ++k) xa[k] = fabsf(x[n * K_DIM + k]);

#pragma unroll
    for (int m = 0; m < M_DIM; ++m) {
        float v = xa[0] + sw[m * K_DIM + 0];
#pragma unroll
        for (int k = 1; k < K_DIM; ++k)
            v = fmaxf(v, xa[k] + sw[m * K_DIM + k]);
        g_midT[m * N_ROWS + n] = v;  // coalesced within each plane
    }
}

// ---------------------------------------------------------------------------
// Stage 2: out[i][j] = max_{m<3}( mid[i][m] + mid[j][m] )
// Block tile: 16 rows (i) x 512 cols (j), 128 threads, 8192 blocks (proven
// best drain granularity). Prologue reduced to THREE aligned LDG.128 per
// thread (SoA planes) + a tiny 48-float sa stage: no j-tile shared array,
// no bank conflicts, minimal sync. Store pattern unchanged: thread = 4
// consecutive j, one STG.128 per row, 512B contiguous per warp.
// ---------------------------------------------------------------------------
#define TILE_I 16
#define TILE_J 512
#define THREADS 128

__global__ __launch_bounds__(THREADS, 16)
void stage2_kernel(float* __restrict__ out) {
    __shared__ float sa[M_DIM * TILE_I];  // sa[m*16 + r]

    const int j0 = blockIdx.x * TILE_J;
    const int i0 = blockIdx.y * TILE_I;
    const int tid = threadIdx.x;

    // i-tile mids: 48 values, one thread each (layout [m][r] -> broadcast reads)
    if (tid < M_DIM * TILE_I) {
        const int m = tid >> 4;        // tid / 16
        const int r = tid & 15;        // tid % 16
        sa[tid] = g_midT[m * N_ROWS + i0 + r];
    }

    // j-tile mids for this thread's 4 columns: one LDG.128 per plane.
    const int jg = j0 + tid * 4;       // global j (16B-aligned)
    const float4 bx = __ldg(reinterpret_cast<const float4*>(&g_midT[0 * N_ROWS + jg]));
    const float4 by = __ldg(reinterpret_cast<const float4*>(&g_midT[1 * N_ROWS + jg]));
    const float4 bz = __ldg(reinterpret_cast<const float4*>(&g_midT[2 * N_ROWS + jg]));

    __syncthreads();

    float4* out4 = reinterpret_cast<float4*>(out + (long)i0 * N_ROWS + jg);
    const long row_stride4 = N_ROWS / 4;  // in float4 units

#pragma unroll 4
    for (int r = 0; r < TILE_I; ++r) {
        const float a0 = sa[0 * TILE_I + r];
        const float a1 = sa[1 * TILE_I + r];
        const float a2 = sa[2 * TILE_I + r];

        float4 v;
        v.x = fmaxf(fmaxf(a0 + bx.x, a1 + by.x), a2 + bz.x);
        v.y = fmaxf(fmaxf(a0 + bx.y, a1 + by.y), a2 + bz.y);
        v.z = fmaxf(fmaxf(a0 + bx.z, a1 + by.z), a2 + bz.z);
        v.w = fmaxf(fmaxf(a0 + bx.w, a1 + by.w), a2 + bz.w);

        out4[(long)r * row_stride4] = v;
    }
}

// ---------------------------------------------------------------------------
extern "C" void kernel_launch(void* const* d_in, const int* in_sizes, int n_in,
                              void* d_out, int out_size) {
    const float* x  = (const float*)d_in[0];   // (8192, 10)
    const float* w1 = (const float*)d_in[1];   // (3, 10)
    float* out = (float*)d_out;                // (8192, 8192)

    stage1_kernel<<<N_ROWS / 256, 256>>>(x, w1);

    dim3 grid(N_ROWS / TILE_J, N_ROWS / TILE_I);  // (16, 512) = 8192 blocks
    stage2_kernel<<<grid, THREADS>>>(out);
}